// round 15
// baseline (speedup 1.0000x reference)
#include <cuda_runtime.h>
#include <cuda_fp16.h>
#include <math.h>
#include <stdint.h>

#define NMAX 100000
#define EMAX 1700000
#define FULLM 0xffffffffu

// Scratch: per-node fp16 P (cols 0..63, includes b1) and Q (64..127). 25.6 MB.
__device__ __half g_PQh[(size_t)NMAX * 128];
__device__ int2 g_edges[EMAX];    // packed (src, dst), input order
__device__ int2 g_sorted[EMAX];   // grouped by dst
__device__ unsigned g_hist[NMAX];
__device__ unsigned g_cursor[NMAX];
__device__ unsigned g_blocksum[128];
__device__ unsigned g_scan_ctr;
__device__ int g_is64;

__device__ __forceinline__ uint32_t smem_u32(const void* p) {
    uint32_t a;
    asm("{ .reg .u64 t; cvta.to.shared.u64 t, %1; cvt.u32.u64 %0, t; }"
        : "=r"(a) : "l"(p));
    return a;
}

// m16n8k16 row.col f32 += f16*f16
__device__ __forceinline__ void mma16816(float* c, const uint32_t* a,
                                         const uint32_t* b) {
    asm volatile(
        "mma.sync.aligned.m16n8k16.row.col.f32.f16.f16.f32 "
        "{%0,%1,%2,%3}, {%4,%5,%6,%7}, {%8,%9}, {%0,%1,%2,%3};"
        : "+f"(c[0]), "+f"(c[1]), "+f"(c[2]), "+f"(c[3])
        : "r"(a[0]), "r"(a[1]), "r"(a[2]), "r"(a[3]), "r"(b[0]), "r"(b[1]));
}

__device__ __forceinline__ void ldmatrix_x4(uint32_t* r, uint32_t addr) {
    asm volatile(
        "ldmatrix.sync.aligned.m8n8.x4.shared.b16 {%0,%1,%2,%3}, [%4];"
        : "=r"(r[0]), "=r"(r[1]), "=r"(r[2]), "=r"(r[3]) : "r"(addr));
}

// ===========================================================================
// Prep: zero dst-histogram + scan counter + init out to -inf bits; block 0
// also detects int64 vs int32 edge_index (jax x64-disabled emits int32).
// Grid covers max(N, n4) at 1024 threads/block.
// ===========================================================================
__global__ __launch_bounds__(1024) void prep_init_kernel(
    const unsigned int* __restrict__ ei, uint4* __restrict__ out,
    int N, int n4) {
    int i = blockIdx.x * 1024 + threadIdx.x;
    if (i < N) g_hist[i] = 0u;
    if (i < n4)
        out[i] = make_uint4(0xff800000u, 0xff800000u, 0xff800000u, 0xff800000u);
    if (blockIdx.x == 0) {
        if (threadIdx.x == 0) g_scan_ctr = 0u;
        __shared__ int any;
        if (threadIdx.x == 0) any = 0;
        __syncthreads();
        if (ei[2 * threadIdx.x + 1] != 0u) any = 1;  // benign race
        __syncthreads();
        if (threadIdx.x == 0) g_is64 = (any == 0) ? 1 : 0;
    }
}

// Fused: edge_index (either width) -> packed int2, + dst histogram.
__global__ void convhist_kernel(const void* __restrict__ eidx, int E) {
    int i = blockIdx.x * blockDim.x + threadIdx.x;
    if (i >= E) return;
    int s, d;
    if (g_is64) {
        const long long* e64 = (const long long*)eidx;
        s = (int)e64[i];
        d = (int)e64[E + i];
    } else {
        const int* e32 = (const int*)eidx;
        s = e32[i];
        d = e32[E + i];
    }
    g_edges[i] = make_int2(s, d);
    atomicAdd(&g_hist[d], 1u);
}

// ===========================================================================
// Exclusive scan of g_hist -> g_cursor (per-block) + block sums; the LAST
// block to finish (decoupled via g_scan_ctr) exclusively scans g_blocksum
// in place. scatter adds g_blocksum[d>>10].
// ===========================================================================
__global__ __launch_bounds__(1024) void scan1_kernel(int N) {
    __shared__ unsigned wsum[32];
    __shared__ int last_s;
    int tid = threadIdx.x, lane = tid & 31, w = tid >> 5;
    int i = blockIdx.x * 1024 + tid;
    unsigned v = (i < N) ? g_hist[i] : 0u;
    unsigned x = v;
#pragma unroll
    for (int o = 1; o < 32; o <<= 1) {
        unsigned y = __shfl_up_sync(FULLM, x, o);
        if (lane >= o) x += y;
    }
    if (lane == 31) wsum[w] = x;
    __syncthreads();
    if (w == 0) {
        unsigned s = wsum[lane];
#pragma unroll
        for (int o = 1; o < 32; o <<= 1) {
            unsigned y = __shfl_up_sync(FULLM, s, o);
            if (lane >= o) s += y;
        }
        wsum[lane] = s;
    }
    __syncthreads();
    unsigned incl = x + (w > 0 ? wsum[w - 1] : 0u);
    if (i < N) g_cursor[i] = incl - v;  // exclusive within block
    if (tid == 1023) g_blocksum[blockIdx.x] = incl;

    // decoupled final scan of block sums by the last-finishing block
    __threadfence();
    __syncthreads();
    if (tid == 0) {
        unsigned c = atomicAdd(&g_scan_ctr, 1u);
        last_s = (c == gridDim.x - 1) ? 1 : 0;
    }
    __syncthreads();
    if (last_s) {
        int nb = gridDim.x;  // <= 128
        unsigned bv = (tid < nb) ? g_blocksum[tid] : 0u;
        unsigned bx = bv;
#pragma unroll
        for (int o = 1; o < 32; o <<= 1) {
            unsigned y = __shfl_up_sync(FULLM, bx, o);
            if (lane >= o) bx += y;
        }
        if (lane == 31) wsum[w] = bx;
        __syncthreads();
        unsigned add = 0;
        for (int j = 0; j < w && j < 4; j++) add += wsum[j];
        if (tid < nb) g_blocksum[tid] = bx + add - bv;  // exclusive
    }
}

__global__ void scatter_kernel(int E) {
    int i = blockIdx.x * blockDim.x + threadIdx.x;
    if (i >= E) return;
    int2 sd = g_edges[i];
    unsigned pos = atomicAdd(&g_cursor[sd.y], 1u) + g_blocksum[sd.y >> 10];
    g_sorted[pos] = sd;
}

// ===========================================================================
// Node kernel: PQ[n] = [ x@(W1a-W1b)+b1 | x@W1b ] in fp16,
// x = [feat(64) | xyz(3)]
// ===========================================================================
__global__ __launch_bounds__(256) void node_pq_kernel(
    const float* __restrict__ xyz, const float* __restrict__ feat,
    const float* __restrict__ W1, const float* __restrict__ b1, int N) {
    __shared__ float ws[67][128];
    __shared__ float xs[32][68];

    int tid = threadIdx.x;
    for (int i = tid; i < 67 * 128; i += 256) {
        int k = i >> 7, c = i & 127;
        float w1b = W1[(k + 67) * 64 + (c & 63)];
        ws[k][c] = (c < 64) ? (W1[k * 64 + c] - w1b) : w1b;
    }
    int n0 = blockIdx.x * 32;
    for (int i = tid; i < 32 * 67; i += 256) {
        int n = i / 67, k = i - n * 67;
        int gn = n0 + n;
        float v = 0.f;
        if (gn < N) v = (k < 64) ? feat[(size_t)gn * 64 + k]
                                 : xyz[(size_t)gn * 3 + (k - 64)];
        xs[n][k] = v;
    }
    __syncthreads();

    int cg = tid & 31, ng = tid >> 5;
    int c0 = cg * 4, nr = ng * 4;
    float acc[4][4];
#pragma unroll
    for (int i = 0; i < 4; i++)
#pragma unroll
        for (int j = 0; j < 4; j++)
            acc[i][j] = (c0 < 64) ? b1[c0 + j] : 0.f;

#pragma unroll 67
    for (int k = 0; k < 67; k++) {
        float4 w = *(const float4*)&ws[k][c0];
#pragma unroll
        for (int i = 0; i < 4; i++) {
            float xv = xs[nr + i][k];
            acc[i][0] = fmaf(xv, w.x, acc[i][0]);
            acc[i][1] = fmaf(xv, w.y, acc[i][1]);
            acc[i][2] = fmaf(xv, w.z, acc[i][2]);
            acc[i][3] = fmaf(xv, w.w, acc[i][3]);
        }
    }
#pragma unroll
    for (int i = 0; i < 4; i++) {
        int gn = n0 + nr + i;
        if (gn < N) {
            __half2 h0 = __floats2half2_rn(acc[i][0], acc[i][1]);
            __half2 h1 = __floats2half2_rn(acc[i][2], acc[i][3]);
            uint2 v = make_uint2(*(uint32_t*)&h0, *(uint32_t*)&h1);
            *(uint2*)&g_PQh[(size_t)gn * 128 + c0] = v;
        }
    }
}

// ===========================================================================
// Finalize: -inf -> 0 (no incoming edges), else add b2[col] (bias commutes
// with max, so it is applied once here instead of per-edge).
// ===========================================================================
__global__ void finalize_kernel(uint4* __restrict__ out,
                                const float* __restrict__ b2, int n4) {
    int i = blockIdx.x * blockDim.x + threadIdx.x;
    if (i >= n4) return;
    uint4 v = out[i];
    float4 b = ((const float4*)b2)[i & 15];  // 16 uint4 per 64-col row
    float4 r;
    r.x = (v.x == 0xff800000u) ? 0.f : __uint_as_float(v.x) + b.x;
    r.y = (v.y == 0xff800000u) ? 0.f : __uint_as_float(v.y) + b.y;
    r.z = (v.z == 0xff800000u) ? 0.f : __uint_as_float(v.z) + b.z;
    r.w = (v.w == 0xff800000u) ? 0.f : __uint_as_float(v.w) + b.w;
    *(float4*)&out[i] = r;
}

// ===========================================================================
// Float atomic max via int/uint ordering trick (no return -> RED).
// ===========================================================================
__device__ __forceinline__ void atomic_max_f(float* a, float v) {
    if (v >= 0.f)
        atomicMax((int*)a, __float_as_int(v));
    else
        atomicMin((unsigned int*)a, __float_as_uint(v));
}

// ===========================================================================
// Edge HMMA kernel, v11: register-resident B fragments. W2 fragments are
// loop-invariant across all ~50K tiles, so they are built ONCE from gmem
// (R4-verified lane mapping) and held in 64 registers -- this removes 16
// ldmatrix issues and 8KB of smem-crossbar traffic per tile (25% of the
// per-SM smem floor). W2 smem tile deleted; dynamic SMEM is now 48KB/CTA
// (per warp 12KB = z0 4K | z1 4K | Cext 4K). launch_bounds(128,3) gives
// ptxas a 170-reg budget (no spills); HW may still place 4 CTAs/SM.
// Otherwise identical to v10: dst-sorted contiguous chunks, fp16 MMA,
// double-buffered z pipeline, SMEM-transpose epilogue, cross-tile running
// max, RED only at dst boundaries.
// ===========================================================================
__global__ __launch_bounds__(128, 3) void edge_mma_kernel(
    const float* __restrict__ W2, float* __restrict__ out, int E) {
    extern __shared__ char dsm[];

    const int tid = threadIdx.x;
    const int lane = tid & 31;
    const int wid = tid >> 5;

    // ---- build register-resident W2^T fragments (single fp16) ----
    // b frag for m16n8k16: lane holds n = nt*8 + lane/4,
    // k = ks*16 + r*8 + (lane%4)*2 (+1). W2 is [k][n] row-major.
    uint32_t bwr[8][4][2];
    {
        const int nn = lane >> 2;
        const int kk = (lane & 3) * 2;
#pragma unroll
        for (int nt = 0; nt < 8; nt++)
#pragma unroll
            for (int ks = 0; ks < 4; ks++)
#pragma unroll
                for (int r = 0; r < 2; r++) {
                    int n = nt * 8 + nn;
                    int k = ks * 16 + r * 8 + kk;
                    __half2 h = __floats2half2_rn(W2[k * 64 + n],
                                                  W2[(k + 1) * 64 + n]);
                    bwr[nt][ks][r] = *(uint32_t*)&h;
                }
    }

    const uint32_t wbuf = smem_u32(&dsm[0]) + (uint32_t)wid * 12288;
    const uint32_t zb0 = wbuf, zb1 = wbuf + 4096, cext = wbuf + 8192;

    // A-frag ldmatrix lane addressing
    const int am = lane >> 3, rowin = lane & 7;
    const uint32_t lswz = (uint32_t)rowin << 4;
    const uint32_t akb = (uint32_t)((am >> 1) << 4);
    const int arow_in = ((am & 1) << 3) + rowin;

    // C-store lane addressing
    const int crow = lane >> 2;                     // fragment row within 8
    const uint32_t ccb = (uint32_t)(lane & 3) * 8;  // col bytes within n-tile

    // cooperative-gather lane pieces: 4 edges per group, 8 lanes per edge
    const int sub = lane >> 3;                // which edge of the quad
    const int cq = lane & 7;                  // 16B chunk within 128B row
    const uint32_t cbyte = (uint32_t)cq * 16; // byte offset in fp16 row

    const __half2 zero2 = __float2half2_rn(0.f);

    // ---- contiguous chunk assignment ----
    const int T = (E + 31) >> 5;
    const int nwarp = gridDim.x * 4;
    const int gw = blockIdx.x * 4 + wid;
    const int chunk = (T + nwarp - 1) / nwarp;
    int t = gw * chunk;
    const int tend = (t + chunk < T) ? t + chunk : T;
    if (t >= tend) return;

    auto gather = [&](int2 sdv, uint32_t zdst) {
#pragma unroll 4
        for (int g = 0; g < 8; g++) {
            int esel = 4 * g + sub;
            int d = __shfl_sync(FULLM, sdv.y, esel);
            int s = __shfl_sync(FULLM, sdv.x, esel);
            uint4 pv = *((const uint4*)(g_PQh + (size_t)d * 128) + cq);
            uint4 qv = *((const uint4*)(g_PQh + (size_t)s * 128 + 64) + cq);
            __half2 z0 = __hmax2(__hadd2(*(__half2*)&pv.x, *(__half2*)&qv.x), zero2);
            __half2 z1 = __hmax2(__hadd2(*(__half2*)&pv.y, *(__half2*)&qv.y), zero2);
            __half2 z2 = __hmax2(__hadd2(*(__half2*)&pv.z, *(__half2*)&qv.z), zero2);
            __half2 z3 = __hmax2(__hadd2(*(__half2*)&pv.w, *(__half2*)&qv.w), zero2);
            uint32_t row = (uint32_t)(4 * g + sub);
            uint32_t off = row * 128 + (cbyte ^ ((row & 7) << 4));
            asm volatile("st.shared.v4.b32 [%0], {%1,%2,%3,%4};"
                         :: "r"(zdst + off),
                            "r"(*(uint32_t*)&z0), "r"(*(uint32_t*)&z1),
                            "r"(*(uint32_t*)&z2), "r"(*(uint32_t*)&z3));
        }
    };

    // ---- pipeline prologue ----
    int e0 = t * 32 + lane;
    int2 sd_cur = g_sorted[(e0 < E) ? e0 : 0];
    gather(sd_cur, zb0);
    int2 sd_nx = sd_cur;
    if (t + 1 < tend) {
        int en = (t + 1) * 32 + lane;
        sd_nx = g_sorted[(en < E) ? en : 0];
    }
    int p = 0;

    // running segmented-max state (carried across tiles)
    int curD = -1;
    float m0 = 0.f, m1 = 0.f;

    for (; t < tend; t++) {
        int e = t * 32 + lane;
        bool valid = (e < E);
        int mydst = valid ? sd_cur.y : -1;
        uint32_t zcur = p ? zb1 : zb0;
        uint32_t znxt = p ? zb0 : zb1;

        __syncwarp();  // prev gather STS visible; prev sweep reads done

        // ---- A fragments for tile t from zcur ----
        uint32_t ah[8][4];  // [mt*4+ks]
#pragma unroll
        for (int mt = 0; mt < 2; mt++) {
            uint32_t rowb = (uint32_t)(mt * 16 + arow_in) * 128;
#pragma unroll
            for (int ks = 0; ks < 4; ks++) {
                uint32_t off = rowb + (((uint32_t)ks * 32 + akb) ^ lswz);
                ldmatrix_x4(ah[mt * 4 + ks], zcur + off);
            }
        }

        // ---- issue next tile's gather (overlaps with MMA below) ----
        bool more = (t + 1 < tend);
        if (more) gather(sd_nx, znxt);
        int2 sd_n2 = sd_nx;
        if (t + 2 < tend) {
            int en2 = (t + 2) * 32 + lane;
            sd_n2 = g_sorted[(en2 < E) ? en2 : 0];
        }

        // ---- MMA + C store (rows 0-15 -> dead zcur, rows 16-31 -> cext) ----
#pragma unroll
        for (int nt = 0; nt < 8; nt++) {
            uint32_t cb = (uint32_t)nt * 32 + ccb;
#pragma unroll
            for (int mt = 0; mt < 2; mt++) {
                float c[4] = {0.f, 0.f, 0.f, 0.f};
#pragma unroll
                for (int ks = 0; ks < 4; ks++)
                    mma16816(c, ah[mt * 4 + ks], bwr[nt][ks]);

                uint32_t chalf = mt ? cext : zcur;
                uint32_t sw = (uint32_t)(crow & 7) << 5;
                uint32_t a0 = chalf + (uint32_t)crow * 256 + (cb ^ sw);
                asm volatile("st.shared.v2.f32 [%0], {%1,%2};"
                             :: "r"(a0), "f"(c[0]), "f"(c[1]));
                asm volatile("st.shared.v2.f32 [%0], {%1,%2};"
                             :: "r"(a0 + 2048), "f"(c[2]), "f"(c[3]));  // +8 rows
            }
        }
        __syncwarp();  // C stores visible before cross-lane reads

        // ---- serial 32-row sweep: running max per col pair, RED at
        //      dst boundaries only ----
#pragma unroll 8
        for (int r = 0; r < 32; r++) {
            int d = __shfl_sync(FULLM, mydst, r);
            uint32_t base = (r < 16) ? zcur : cext;
            uint32_t off = base + (uint32_t)(r & 15) * 256 +
                           (((uint32_t)lane * 8) ^ ((uint32_t)(r & 7) << 5));
            float y0, y1;
            asm volatile("ld.shared.v2.f32 {%0,%1}, [%2];"
                         : "=f"(y0), "=f"(y1) : "r"(off));
            if (d < 0) continue;  // trailing invalid rows
            if (d != curD) {
                if (curD >= 0) {
                    float* o = out + (size_t)curD * 64 + lane * 2;
                    atomic_max_f(o, m0);
                    atomic_max_f(o + 1, m1);
                }
                curD = d;
                m0 = y0;
                m1 = y1;
            } else {
                m0 = fmaxf(m0, y0);
                m1 = fmaxf(m1, y1);
            }
        }

        // ---- rotate pipeline ----
        sd_cur = sd_nx;
        sd_nx = sd_n2;
        p ^= 1;
    }

    // ---- final flush ----
    if (curD >= 0) {
        float* o = out + (size_t)curD * 64 + lane * 2;
        atomic_max_f(o, m0);
        atomic_max_f(o + 1, m1);
    }
}

#define EDGE_DSMEM (4 * 12288)

// ===========================================================================
// Inputs: [0]=xyz (N*3 f32), [1]=feat (N*64 f32), [2]=edge_index (2*E int),
//         [3]=W1 (134*64 f32), [4]=b1 (64), [5]=W2 (64*64), [6]=b2 (64)
// ===========================================================================
extern "C" void kernel_launch(void* const* d_in, const int* in_sizes, int n_in,
                              void* d_out, int out_size) {
    const float* xyz  = (const float*)d_in[0];
    const float* feat = (const float*)d_in[1];
    const void*  eidx = d_in[2];
    const float* W1   = (const float*)d_in[3];
    const float* b1   = (const float*)d_in[4];
    const float* W2   = (const float*)d_in[5];
    const float* b2   = (const float*)d_in[6];
    float* out = (float*)d_out;

    int N = in_sizes[0] / 3;
    int E = in_sizes[2] / 2;
    int outn = N * 64;
    int n4 = outn / 4;
    int nb = (N + 1023) / 1024;
    int nbig = (n4 > N ? n4 : N);
    int nbp = (nbig + 1023) / 1024;

    cudaFuncSetAttribute(edge_mma_kernel,
                         cudaFuncAttributeMaxDynamicSharedMemorySize,
                         EDGE_DSMEM);

    prep_init_kernel<<<nbp, 1024>>>((const unsigned int*)eidx, (uint4*)out,
                                    N, n4);
    convhist_kernel<<<(E + 255) / 256, 256>>>(eidx, E);
    scan1_kernel<<<nb, 1024>>>(N);
    scatter_kernel<<<(E + 255) / 256, 256>>>(E);
    node_pq_kernel<<<(N + 31) / 32, 256>>>(xyz, feat, W1, b1, N);

    int Twarp = (E + 31) >> 5;
    int grid = 4 * 148;  // persistent, 4 CTAs/SM worth of warps
    if (grid > (Twarp + 3) / 4) grid = (Twarp + 3) / 4;
    edge_mma_kernel<<<grid, 128, EDGE_DSMEM>>>(W2, out, E);

    finalize_kernel<<<(n4 + 255) / 256, 256>>>((uint4*)out, b2, n4);
}

// round 16
// speedup vs baseline: 1.3884x; 1.3884x over previous
#include <cuda_runtime.h>
#include <cuda_fp16.h>
#include <math.h>
#include <stdint.h>

#define NMAX 100000
#define EMAX 1700000
#define FULLM 0xffffffffu

// Scratch: per-node fp16 P (cols 0..63, includes b1) and Q (64..127). 25.6 MB.
__device__ __half g_PQh[(size_t)NMAX * 128];
__device__ int2 g_edges[EMAX];    // packed (src, dst), input order
__device__ int2 g_sorted[EMAX];   // grouped by dst
__device__ unsigned g_hist[NMAX];
__device__ unsigned g_cursor[NMAX];
__device__ unsigned g_blocksum[128];
__device__ unsigned g_scan_ctr;
__device__ int g_is64;

__device__ __forceinline__ uint32_t smem_u32(const void* p) {
    uint32_t a;
    asm("{ .reg .u64 t; cvta.to.shared.u64 t, %1; cvt.u32.u64 %0, t; }"
        : "=r"(a) : "l"(p));
    return a;
}

// m16n8k16 row.col f32 += f16*f16
__device__ __forceinline__ void mma16816(float* c, const uint32_t* a,
                                         const uint32_t* b) {
    asm volatile(
        "mma.sync.aligned.m16n8k16.row.col.f32.f16.f16.f32 "
        "{%0,%1,%2,%3}, {%4,%5,%6,%7}, {%8,%9}, {%0,%1,%2,%3};"
        : "+f"(c[0]), "+f"(c[1]), "+f"(c[2]), "+f"(c[3])
        : "r"(a[0]), "r"(a[1]), "r"(a[2]), "r"(a[3]), "r"(b[0]), "r"(b[1]));
}

__device__ __forceinline__ void ldmatrix_x4(uint32_t* r, uint32_t addr) {
    asm volatile(
        "ldmatrix.sync.aligned.m8n8.x4.shared.b16 {%0,%1,%2,%3}, [%4];"
        : "=r"(r[0]), "=r"(r[1]), "=r"(r[2]), "=r"(r[3]) : "r"(addr));
}

// ===========================================================================
// Prep: zero dst-histogram + scan counter + init out to -inf bits; block 0
// also detects int64 vs int32 edge_index (jax x64-disabled emits int32).
// Grid covers max(N, n4) at 1024 threads/block.
// ===========================================================================
__global__ __launch_bounds__(1024) void prep_init_kernel(
    const unsigned int* __restrict__ ei, uint4* __restrict__ out,
    int N, int n4) {
    int i = blockIdx.x * 1024 + threadIdx.x;
    if (i < N) g_hist[i] = 0u;
    if (i < n4)
        out[i] = make_uint4(0xff800000u, 0xff800000u, 0xff800000u, 0xff800000u);
    if (blockIdx.x == 0) {
        if (threadIdx.x == 0) g_scan_ctr = 0u;
        __shared__ int any;
        if (threadIdx.x == 0) any = 0;
        __syncthreads();
        if (ei[2 * threadIdx.x + 1] != 0u) any = 1;  // benign race
        __syncthreads();
        if (threadIdx.x == 0) g_is64 = (any == 0) ? 1 : 0;
    }
}

// Fused: edge_index (either width) -> packed int2, + dst histogram.
__global__ void convhist_kernel(const void* __restrict__ eidx, int E) {
    int i = blockIdx.x * blockDim.x + threadIdx.x;
    if (i >= E) return;
    int s, d;
    if (g_is64) {
        const long long* e64 = (const long long*)eidx;
        s = (int)e64[i];
        d = (int)e64[E + i];
    } else {
        const int* e32 = (const int*)eidx;
        s = e32[i];
        d = e32[E + i];
    }
    g_edges[i] = make_int2(s, d);
    atomicAdd(&g_hist[d], 1u);
}

// ===========================================================================
// Exclusive scan of g_hist -> g_cursor (per-block) + block sums; the LAST
// block to finish (decoupled via g_scan_ctr) exclusively scans g_blocksum
// in place. scatter adds g_blocksum[d>>10].
// ===========================================================================
__global__ __launch_bounds__(1024) void scan1_kernel(int N) {
    __shared__ unsigned wsum[32];
    __shared__ int last_s;
    int tid = threadIdx.x, lane = tid & 31, w = tid >> 5;
    int i = blockIdx.x * 1024 + tid;
    unsigned v = (i < N) ? g_hist[i] : 0u;
    unsigned x = v;
#pragma unroll
    for (int o = 1; o < 32; o <<= 1) {
        unsigned y = __shfl_up_sync(FULLM, x, o);
        if (lane >= o) x += y;
    }
    if (lane == 31) wsum[w] = x;
    __syncthreads();
    if (w == 0) {
        unsigned s = wsum[lane];
#pragma unroll
        for (int o = 1; o < 32; o <<= 1) {
            unsigned y = __shfl_up_sync(FULLM, s, o);
            if (lane >= o) s += y;
        }
        wsum[lane] = s;
    }
    __syncthreads();
    unsigned incl = x + (w > 0 ? wsum[w - 1] : 0u);
    if (i < N) g_cursor[i] = incl - v;  // exclusive within block
    if (tid == 1023) g_blocksum[blockIdx.x] = incl;

    // decoupled final scan of block sums by the last-finishing block
    __threadfence();
    __syncthreads();
    if (tid == 0) {
        unsigned c = atomicAdd(&g_scan_ctr, 1u);
        last_s = (c == gridDim.x - 1) ? 1 : 0;
    }
    __syncthreads();
    if (last_s) {
        int nb = gridDim.x;  // <= 128
        unsigned bv = (tid < nb) ? g_blocksum[tid] : 0u;
        unsigned bx = bv;
#pragma unroll
        for (int o = 1; o < 32; o <<= 1) {
            unsigned y = __shfl_up_sync(FULLM, bx, o);
            if (lane >= o) bx += y;
        }
        if (lane == 31) wsum[w] = bx;
        __syncthreads();
        unsigned add = 0;
        for (int j = 0; j < w && j < 4; j++) add += wsum[j];
        if (tid < nb) g_blocksum[tid] = bx + add - bv;  // exclusive
    }
}

__global__ void scatter_kernel(int E) {
    int i = blockIdx.x * blockDim.x + threadIdx.x;
    if (i >= E) return;
    int2 sd = g_edges[i];
    unsigned pos = atomicAdd(&g_cursor[sd.y], 1u) + g_blocksum[sd.y >> 10];
    g_sorted[pos] = sd;
}

// ===========================================================================
// Node kernel: PQ[n] = [ x@(W1a-W1b)+b1 | x@W1b ] in fp16,
// x = [feat(64) | xyz(3)]
// ===========================================================================
__global__ __launch_bounds__(256) void node_pq_kernel(
    const float* __restrict__ xyz, const float* __restrict__ feat,
    const float* __restrict__ W1, const float* __restrict__ b1, int N) {
    __shared__ float ws[67][128];
    __shared__ float xs[32][68];

    int tid = threadIdx.x;
    for (int i = tid; i < 67 * 128; i += 256) {
        int k = i >> 7, c = i & 127;
        float w1b = W1[(k + 67) * 64 + (c & 63)];
        ws[k][c] = (c < 64) ? (W1[k * 64 + c] - w1b) : w1b;
    }
    int n0 = blockIdx.x * 32;
    for (int i = tid; i < 32 * 67; i += 256) {
        int n = i / 67, k = i - n * 67;
        int gn = n0 + n;
        float v = 0.f;
        if (gn < N) v = (k < 64) ? feat[(size_t)gn * 64 + k]
                                 : xyz[(size_t)gn * 3 + (k - 64)];
        xs[n][k] = v;
    }
    __syncthreads();

    int cg = tid & 31, ng = tid >> 5;
    int c0 = cg * 4, nr = ng * 4;
    float acc[4][4];
#pragma unroll
    for (int i = 0; i < 4; i++)
#pragma unroll
        for (int j = 0; j < 4; j++)
            acc[i][j] = (c0 < 64) ? b1[c0 + j] : 0.f;

#pragma unroll 67
    for (int k = 0; k < 67; k++) {
        float4 w = *(const float4*)&ws[k][c0];
#pragma unroll
        for (int i = 0; i < 4; i++) {
            float xv = xs[nr + i][k];
            acc[i][0] = fmaf(xv, w.x, acc[i][0]);
            acc[i][1] = fmaf(xv, w.y, acc[i][1]);
            acc[i][2] = fmaf(xv, w.z, acc[i][2]);
            acc[i][3] = fmaf(xv, w.w, acc[i][3]);
        }
    }
#pragma unroll
    for (int i = 0; i < 4; i++) {
        int gn = n0 + nr + i;
        if (gn < N) {
            __half2 h0 = __floats2half2_rn(acc[i][0], acc[i][1]);
            __half2 h1 = __floats2half2_rn(acc[i][2], acc[i][3]);
            uint2 v = make_uint2(*(uint32_t*)&h0, *(uint32_t*)&h1);
            *(uint2*)&g_PQh[(size_t)gn * 128 + c0] = v;
        }
    }
}

// ===========================================================================
// Finalize: -inf -> 0 (no incoming edges), else add b2[col] (bias commutes
// with max, so it is applied once here instead of per-edge).
// ===========================================================================
__global__ void finalize_kernel(uint4* __restrict__ out,
                                const float* __restrict__ b2, int n4) {
    int i = blockIdx.x * blockDim.x + threadIdx.x;
    if (i >= n4) return;
    uint4 v = out[i];
    float4 b = ((const float4*)b2)[i & 15];  // 16 uint4 per 64-col row
    float4 r;
    r.x = (v.x == 0xff800000u) ? 0.f : __uint_as_float(v.x) + b.x;
    r.y = (v.y == 0xff800000u) ? 0.f : __uint_as_float(v.y) + b.y;
    r.z = (v.z == 0xff800000u) ? 0.f : __uint_as_float(v.z) + b.z;
    r.w = (v.w == 0xff800000u) ? 0.f : __uint_as_float(v.w) + b.w;
    *(float4*)&out[i] = r;
}

// ===========================================================================
// Float atomic max via int/uint ordering trick (no return -> RED).
// ===========================================================================
__device__ __forceinline__ void atomic_max_f(float* a, float v) {
    if (v >= 0.f)
        atomicMax((int*)a, __float_as_int(v));
    else
        atomicMin((unsigned int*)a, __float_as_uint(v));
}

// ===========================================================================
// Edge HMMA kernel, v10 (reverted from v11: register-resident B fragments
// caused spills / occupancy loss and a 95us regression; smem-crossbar
// bandwidth is cheaper than registers here).
// Software-pipelined tiles (double-buffered z). While tile t runs
// ldmatrix+MMA+sweep, tile t+1's gather LDGs are in flight into the other
// z buffer. Dynamic SMEM 56KB/CTA: [0,8K) W2^T fp16; per warp 12KB =
// z0 4K | z1 4K | Cext 4K. C rows 0-15 alias the DEAD current-z buffer,
// rows 16-31 -> Cext. 4 CTAs/SM. dst-sorted contiguous chunks, fp16 MMA,
// SMEM-transpose epilogue, cross-tile running max, RED at dst boundaries.
// ===========================================================================
__global__ __launch_bounds__(128, 4) void edge_mma_kernel(
    const float* __restrict__ W2, float* __restrict__ out, int E) {
    extern __shared__ char dsm[];

    const int tid = threadIdx.x;
    const int lane = tid & 31;
    const int wid = tid >> 5;

    // ---- build swizzled W2^T fp16 in SMEM (once per CTA) ----
    for (int i = tid; i < 64 * 64; i += 128) {
        int n = i >> 6, k = i & 63;
        float w = W2[k * 64 + n];
        uint32_t off = (uint32_t)n * 128 + (((uint32_t)(2 * k)) ^ ((uint32_t)(n & 7) << 4));
        *(__half*)(&dsm[off]) = __float2half_rn(w);
    }
    __syncthreads();

    const uint32_t w_base = smem_u32(&dsm[0]);
    const uint32_t wbuf = w_base + 8192 + (uint32_t)wid * 12288;
    const uint32_t zb0 = wbuf, zb1 = wbuf + 4096, cext = wbuf + 8192;

    // B-frag ldmatrix lane addressing (covers ks pair per x4)
    const uint32_t brow = lane & 7;
    const uint32_t bswz = brow << 4;
    const uint32_t bpart = (((uint32_t)lane >> 3) & 1) * 16 + (((uint32_t)lane >> 4) & 1) * 32;
    const uint32_t boff0 = brow * 128 + (bpart ^ bswz);        // ks0,ks1
    const uint32_t boff1 = brow * 128 + ((bpart + 64) ^ bswz); // ks2,ks3

    // A-frag ldmatrix lane addressing
    const int am = lane >> 3, rowin = lane & 7;
    const uint32_t lswz = (uint32_t)rowin << 4;
    const uint32_t akb = (uint32_t)((am >> 1) << 4);
    const int arow_in = ((am & 1) << 3) + rowin;

    // C-store lane addressing
    const int crow = lane >> 2;                     // fragment row within 8
    const uint32_t ccb = (uint32_t)(lane & 3) * 8;  // col bytes within n-tile

    // cooperative-gather lane pieces: 4 edges per group, 8 lanes per edge
    const int sub = lane >> 3;                // which edge of the quad
    const int cq = lane & 7;                  // 16B chunk within 128B row
    const uint32_t cbyte = (uint32_t)cq * 16; // byte offset in fp16 row

    const __half2 zero2 = __float2half2_rn(0.f);

    // ---- contiguous chunk assignment ----
    const int T = (E + 31) >> 5;
    const int nwarp = gridDim.x * 4;
    const int gw = blockIdx.x * 4 + wid;
    const int chunk = (T + nwarp - 1) / nwarp;
    int t = gw * chunk;
    const int tend = (t + chunk < T) ? t + chunk : T;
    if (t >= tend) return;

    // gather macro-equivalent lambda
    auto gather = [&](int2 sdv, uint32_t zdst) {
#pragma unroll 4
        for (int g = 0; g < 8; g++) {
            int esel = 4 * g + sub;
            int d = __shfl_sync(FULLM, sdv.y, esel);
            int s = __shfl_sync(FULLM, sdv.x, esel);
            uint4 pv = *((const uint4*)(g_PQh + (size_t)d * 128) + cq);
            uint4 qv = *((const uint4*)(g_PQh + (size_t)s * 128 + 64) + cq);
            __half2 z0 = __hmax2(__hadd2(*(__half2*)&pv.x, *(__half2*)&qv.x), zero2);
            __half2 z1 = __hmax2(__hadd2(*(__half2*)&pv.y, *(__half2*)&qv.y), zero2);
            __half2 z2 = __hmax2(__hadd2(*(__half2*)&pv.z, *(__half2*)&qv.z), zero2);
            __half2 z3 = __hmax2(__hadd2(*(__half2*)&pv.w, *(__half2*)&qv.w), zero2);
            uint32_t row = (uint32_t)(4 * g + sub);
            uint32_t off = row * 128 + (cbyte ^ ((row & 7) << 4));
            asm volatile("st.shared.v4.b32 [%0], {%1,%2,%3,%4};"
                         :: "r"(zdst + off),
                            "r"(*(uint32_t*)&z0), "r"(*(uint32_t*)&z1),
                            "r"(*(uint32_t*)&z2), "r"(*(uint32_t*)&z3));
        }
    };

    // ---- pipeline prologue ----
    int e0 = t * 32 + lane;
    int2 sd_cur = g_sorted[(e0 < E) ? e0 : 0];
    gather(sd_cur, zb0);
    int2 sd_nx = sd_cur;
    if (t + 1 < tend) {
        int en = (t + 1) * 32 + lane;
        sd_nx = g_sorted[(en < E) ? en : 0];
    }
    int p = 0;

    // running segmented-max state (carried across tiles)
    int curD = -1;
    float m0 = 0.f, m1 = 0.f;

    for (; t < tend; t++) {
        int e = t * 32 + lane;
        bool valid = (e < E);
        int mydst = valid ? sd_cur.y : -1;
        uint32_t zcur = p ? zb1 : zb0;
        uint32_t znxt = p ? zb0 : zb1;

        __syncwarp();  // prev gather STS visible; prev sweep reads done

        // ---- A fragments for tile t from zcur ----
        uint32_t ah[8][4];  // [mt*4+ks]
#pragma unroll
        for (int mt = 0; mt < 2; mt++) {
            uint32_t rowb = (uint32_t)(mt * 16 + arow_in) * 128;
#pragma unroll
            for (int ks = 0; ks < 4; ks++) {
                uint32_t off = rowb + (((uint32_t)ks * 32 + akb) ^ lswz);
                ldmatrix_x4(ah[mt * 4 + ks], zcur + off);
            }
        }

        // ---- issue next tile's gather (overlaps with MMA below) ----
        bool more = (t + 1 < tend);
        if (more) gather(sd_nx, znxt);
        int2 sd_n2 = sd_nx;
        if (t + 2 < tend) {
            int en2 = (t + 2) * 32 + lane;
            sd_n2 = g_sorted[(en2 < E) ? en2 : 0];
        }

        // ---- MMA + C store (rows 0-15 -> dead zcur, rows 16-31 -> cext) ----
#pragma unroll
        for (int nt = 0; nt < 8; nt++) {
            uint32_t bw[4][2];
            uint32_t wb = (uint32_t)nt * 1024;
            ldmatrix_x4(&bw[0][0], w_base + wb + boff0);
            ldmatrix_x4(&bw[2][0], w_base + wb + boff1);
            uint32_t cb = (uint32_t)nt * 32 + ccb;
#pragma unroll
            for (int mt = 0; mt < 2; mt++) {
                float c[4] = {0.f, 0.f, 0.f, 0.f};
#pragma unroll
                for (int ks = 0; ks < 4; ks++) mma16816(c, ah[mt * 4 + ks], bw[ks]);

                uint32_t chalf = mt ? cext : zcur;
                uint32_t sw = (uint32_t)(crow & 7) << 5;
                uint32_t a0 = chalf + (uint32_t)crow * 256 + (cb ^ sw);
                asm volatile("st.shared.v2.f32 [%0], {%1,%2};"
                             :: "r"(a0), "f"(c[0]), "f"(c[1]));
                asm volatile("st.shared.v2.f32 [%0], {%1,%2};"
                             :: "r"(a0 + 2048), "f"(c[2]), "f"(c[3]));  // +8 rows
            }
        }
        __syncwarp();  // C stores visible before cross-lane reads

        // ---- serial 32-row sweep: running max per col pair, RED at
        //      dst boundaries only ----
#pragma unroll 8
        for (int r = 0; r < 32; r++) {
            int d = __shfl_sync(FULLM, mydst, r);
            uint32_t base = (r < 16) ? zcur : cext;
            uint32_t off = base + (uint32_t)(r & 15) * 256 +
                           (((uint32_t)lane * 8) ^ ((uint32_t)(r & 7) << 5));
            float y0, y1;
            asm volatile("ld.shared.v2.f32 {%0,%1}, [%2];"
                         : "=f"(y0), "=f"(y1) : "r"(off));
            if (d < 0) continue;  // trailing invalid rows
            if (d != curD) {
                if (curD >= 0) {
                    float* o = out + (size_t)curD * 64 + lane * 2;
                    atomic_max_f(o, m0);
                    atomic_max_f(o + 1, m1);
                }
                curD = d;
                m0 = y0;
                m1 = y1;
            } else {
                m0 = fmaxf(m0, y0);
                m1 = fmaxf(m1, y1);
            }
        }

        // ---- rotate pipeline ----
        sd_cur = sd_nx;
        sd_nx = sd_n2;
        p ^= 1;
    }

    // ---- final flush ----
    if (curD >= 0) {
        float* o = out + (size_t)curD * 64 + lane * 2;
        atomic_max_f(o, m0);
        atomic_max_f(o + 1, m1);
    }
}

#define EDGE_DSMEM (8192 + 4 * 12288)

// ===========================================================================
// Inputs: [0]=xyz (N*3 f32), [1]=feat (N*64 f32), [2]=edge_index (2*E int),
//         [3]=W1 (134*64 f32), [4]=b1 (64), [5]=W2 (64*64), [6]=b2 (64)
// Launch DAG (multi-stream fork/join, graph-capturable):
//   s0: prep_init -> convhist -> scan1 -> scatter ─┐
//   s2: (fork) node_pq ────────────────────────────┴→ edge -> finalize
// ===========================================================================
extern "C" void kernel_launch(void* const* d_in, const int* in_sizes, int n_in,
                              void* d_out, int out_size) {
    const float* xyz  = (const float*)d_in[0];
    const float* feat = (const float*)d_in[1];
    const void*  eidx = d_in[2];
    const float* W1   = (const float*)d_in[3];
    const float* b1   = (const float*)d_in[4];
    const float* W2   = (const float*)d_in[5];
    const float* b2   = (const float*)d_in[6];
    float* out = (float*)d_out;

    int N = in_sizes[0] / 3;
    int E = in_sizes[2] / 2;
    int outn = N * 64;
    int n4 = outn / 4;
    int nb = (N + 1023) / 1024;
    int nbig = (n4 > N ? n4 : N);
    int nbp = (nbig + 1023) / 1024;

    static int inited = 0;
    static cudaStream_t s2;
    static cudaEvent_t evFork, evJoin;
    if (!inited) {
        cudaFuncSetAttribute(edge_mma_kernel,
                             cudaFuncAttributeMaxDynamicSharedMemorySize,
                             EDGE_DSMEM);
        cudaStreamCreateWithFlags(&s2, cudaStreamNonBlocking);
        cudaEventCreateWithFlags(&evFork, cudaEventDisableTiming);
        cudaEventCreateWithFlags(&evJoin, cudaEventDisableTiming);
        inited = 1;
    }

    // fork: node_pq on side stream (independent of the sort chain)
    cudaEventRecord(evFork, 0);
    cudaStreamWaitEvent(s2, evFork, 0);
    node_pq_kernel<<<(N + 31) / 32, 256, 0, s2>>>(xyz, feat, W1, b1, N);
    cudaEventRecord(evJoin, s2);

    // main chain
    prep_init_kernel<<<nbp, 1024>>>((const unsigned int*)eidx, (uint4*)out,
                                    N, n4);
    convhist_kernel<<<(E + 255) / 256, 256>>>(eidx, E);
    scan1_kernel<<<nb, 1024>>>(N);
    scatter_kernel<<<(E + 255) / 256, 256>>>(E);

    // join: edge needs both g_sorted (main) and g_PQh (side)
    cudaStreamWaitEvent(0, evJoin, 0);

    int Twarp = (E + 31) >> 5;
    int grid = 4 * 148;  // persistent, 4 CTAs/SM
    if (grid > (Twarp + 3) / 4) grid = (Twarp + 3) / 4;
    edge_mma_kernel<<<grid, 128, EDGE_DSMEM>>>(W2, out, E);

    finalize_kernel<<<(n4 + 255) / 256, 256>>>((uint4*)out, b2, n4);
}

// round 17
// speedup vs baseline: 1.4506x; 1.0448x over previous
#include <cuda_runtime.h>
#include <cuda_fp16.h>
#include <math.h>
#include <stdint.h>

#define NMAX 100000
#define EMAX 1700000
#define FULLM 0xffffffffu

// Scratch: per-node fp16 P (cols 0..63, includes b1) and Q (64..127). 25.6 MB.
__device__ __half g_PQh[(size_t)NMAX * 128];
__device__ int2 g_edges[EMAX];    // packed (src, dst), input order
__device__ int2 g_sorted[EMAX];   // grouped by dst
__device__ unsigned g_hist[NMAX];
__device__ unsigned g_cursor[NMAX];
__device__ unsigned g_blocksum[128];
__device__ unsigned g_scan_ctr;
__device__ int g_is64;

__device__ __forceinline__ uint32_t smem_u32(const void* p) {
    uint32_t a;
    asm("{ .reg .u64 t; cvta.to.shared.u64 t, %1; cvt.u32.u64 %0, t; }"
        : "=r"(a) : "l"(p));
    return a;
}

// m16n8k16 row.col f32 += f16*f16
__device__ __forceinline__ void mma16816(float* c, const uint32_t* a,
                                         const uint32_t* b) {
    asm volatile(
        "mma.sync.aligned.m16n8k16.row.col.f32.f16.f16.f32 "
        "{%0,%1,%2,%3}, {%4,%5,%6,%7}, {%8,%9}, {%0,%1,%2,%3};"
        : "+f"(c[0]), "+f"(c[1]), "+f"(c[2]), "+f"(c[3])
        : "r"(a[0]), "r"(a[1]), "r"(a[2]), "r"(a[3]), "r"(b[0]), "r"(b[1]));
}

__device__ __forceinline__ void ldmatrix_x4(uint32_t* r, uint32_t addr) {
    asm volatile(
        "ldmatrix.sync.aligned.m8n8.x4.shared.b16 {%0,%1,%2,%3}, [%4];"
        : "=r"(r[0]), "=r"(r[1]), "=r"(r[2]), "=r"(r[3]) : "r"(addr));
}

// ===========================================================================
// Prep: zero dst-histogram + scan counter + init out to -inf bits; block 0
// also detects int64 vs int32 edge_index (jax x64-disabled emits int32).
// ===========================================================================
__global__ __launch_bounds__(1024) void prep_init_kernel(
    const unsigned int* __restrict__ ei, uint4* __restrict__ out,
    int N, int n4) {
    int i = blockIdx.x * 1024 + threadIdx.x;
    if (i < N) g_hist[i] = 0u;
    if (i < n4)
        out[i] = make_uint4(0xff800000u, 0xff800000u, 0xff800000u, 0xff800000u);
    if (blockIdx.x == 0) {
        if (threadIdx.x == 0) g_scan_ctr = 0u;
        __shared__ int any;
        if (threadIdx.x == 0) any = 0;
        __syncthreads();
        if (ei[2 * threadIdx.x + 1] != 0u) any = 1;  // benign race
        __syncthreads();
        if (threadIdx.x == 0) g_is64 = (any == 0) ? 1 : 0;
    }
}

// Fused: edge_index (either width) -> packed int2, + dst histogram.
__global__ void convhist_kernel(const void* __restrict__ eidx, int E) {
    int i = blockIdx.x * blockDim.x + threadIdx.x;
    if (i >= E) return;
    int s, d;
    if (g_is64) {
        const long long* e64 = (const long long*)eidx;
        s = (int)e64[i];
        d = (int)e64[E + i];
    } else {
        const int* e32 = (const int*)eidx;
        s = e32[i];
        d = e32[E + i];
    }
    g_edges[i] = make_int2(s, d);
    atomicAdd(&g_hist[d], 1u);
}

// ===========================================================================
// Exclusive scan of g_hist -> g_cursor (per-block) + block sums; the LAST
// block to finish (decoupled via g_scan_ctr) exclusively scans g_blocksum
// in place. scatter adds g_blocksum[d>>10].
// ===========================================================================
__global__ __launch_bounds__(1024) void scan1_kernel(int N) {
    __shared__ unsigned wsum[32];
    __shared__ int last_s;
    int tid = threadIdx.x, lane = tid & 31, w = tid >> 5;
    int i = blockIdx.x * 1024 + tid;
    unsigned v = (i < N) ? g_hist[i] : 0u;
    unsigned x = v;
#pragma unroll
    for (int o = 1; o < 32; o <<= 1) {
        unsigned y = __shfl_up_sync(FULLM, x, o);
        if (lane >= o) x += y;
    }
    if (lane == 31) wsum[w] = x;
    __syncthreads();
    if (w == 0) {
        unsigned s = wsum[lane];
#pragma unroll
        for (int o = 1; o < 32; o <<= 1) {
            unsigned y = __shfl_up_sync(FULLM, s, o);
            if (lane >= o) s += y;
        }
        wsum[lane] = s;
    }
    __syncthreads();
    unsigned incl = x + (w > 0 ? wsum[w - 1] : 0u);
    if (i < N) g_cursor[i] = incl - v;  // exclusive within block
    if (tid == 1023) g_blocksum[blockIdx.x] = incl;

    // decoupled final scan of block sums by the last-finishing block
    __threadfence();
    __syncthreads();
    if (tid == 0) {
        unsigned c = atomicAdd(&g_scan_ctr, 1u);
        last_s = (c == gridDim.x - 1) ? 1 : 0;
    }
    __syncthreads();
    if (last_s) {
        int nb = gridDim.x;  // <= 128
        unsigned bv = (tid < nb) ? g_blocksum[tid] : 0u;
        unsigned bx = bv;
#pragma unroll
        for (int o = 1; o < 32; o <<= 1) {
            unsigned y = __shfl_up_sync(FULLM, bx, o);
            if (lane >= o) bx += y;
        }
        if (lane == 31) wsum[w] = bx;
        __syncthreads();
        unsigned add = 0;
        for (int j = 0; j < w && j < 4; j++) add += wsum[j];
        if (tid < nb) g_blocksum[tid] = bx + add - bv;  // exclusive
    }
}

__global__ void scatter_kernel(int E) {
    int i = blockIdx.x * blockDim.x + threadIdx.x;
    if (i >= E) return;
    int2 sd = g_edges[i];
    unsigned pos = atomicAdd(&g_cursor[sd.y], 1u) + g_blocksum[sd.y >> 10];
    g_sorted[pos] = sd;
}

// ===========================================================================
// Node kernel: PQ[n] = [ x@(W1a-W1b)+b1 | x@W1b ] in fp16,
// x = [feat(64) | xyz(3)]
// ===========================================================================
__global__ __launch_bounds__(256) void node_pq_kernel(
    const float* __restrict__ xyz, const float* __restrict__ feat,
    const float* __restrict__ W1, const float* __restrict__ b1, int N) {
    __shared__ float ws[67][128];
    __shared__ float xs[32][68];

    int tid = threadIdx.x;
    for (int i = tid; i < 67 * 128; i += 256) {
        int k = i >> 7, c = i & 127;
        float w1b = W1[(k + 67) * 64 + (c & 63)];
        ws[k][c] = (c < 64) ? (W1[k * 64 + c] - w1b) : w1b;
    }
    int n0 = blockIdx.x * 32;
    for (int i = tid; i < 32 * 67; i += 256) {
        int n = i / 67, k = i - n * 67;
        int gn = n0 + n;
        float v = 0.f;
        if (gn < N) v = (k < 64) ? feat[(size_t)gn * 64 + k]
                                 : xyz[(size_t)gn * 3 + (k - 64)];
        xs[n][k] = v;
    }
    __syncthreads();

    int cg = tid & 31, ng = tid >> 5;
    int c0 = cg * 4, nr = ng * 4;
    float acc[4][4];
#pragma unroll
    for (int i = 0; i < 4; i++)
#pragma unroll
        for (int j = 0; j < 4; j++)
            acc[i][j] = (c0 < 64) ? b1[c0 + j] : 0.f;

#pragma unroll 67
    for (int k = 0; k < 67; k++) {
        float4 w = *(const float4*)&ws[k][c0];
#pragma unroll
        for (int i = 0; i < 4; i++) {
            float xv = xs[nr + i][k];
            acc[i][0] = fmaf(xv, w.x, acc[i][0]);
            acc[i][1] = fmaf(xv, w.y, acc[i][1]);
            acc[i][2] = fmaf(xv, w.z, acc[i][2]);
            acc[i][3] = fmaf(xv, w.w, acc[i][3]);
        }
    }
#pragma unroll
    for (int i = 0; i < 4; i++) {
        int gn = n0 + nr + i;
        if (gn < N) {
            __half2 h0 = __floats2half2_rn(acc[i][0], acc[i][1]);
            __half2 h1 = __floats2half2_rn(acc[i][2], acc[i][3]);
            uint2 v = make_uint2(*(uint32_t*)&h0, *(uint32_t*)&h1);
            *(uint2*)&g_PQh[(size_t)gn * 128 + c0] = v;
        }
    }
}

// ===========================================================================
// Finalize: -inf -> 0 (no incoming edges), else add b2[col] (bias commutes
// with max, so it is applied once here instead of per-edge).
// ===========================================================================
__global__ void finalize_kernel(uint4* __restrict__ out,
                                const float* __restrict__ b2, int n4) {
    int i = blockIdx.x * blockDim.x + threadIdx.x;
    if (i >= n4) return;
    uint4 v = out[i];
    float4 b = ((const float4*)b2)[i & 15];  // 16 uint4 per 64-col row
    float4 r;
    r.x = (v.x == 0xff800000u) ? 0.f : __uint_as_float(v.x) + b.x;
    r.y = (v.y == 0xff800000u) ? 0.f : __uint_as_float(v.y) + b.y;
    r.z = (v.z == 0xff800000u) ? 0.f : __uint_as_float(v.z) + b.z;
    r.w = (v.w == 0xff800000u) ? 0.f : __uint_as_float(v.w) + b.w;
    *(float4*)&out[i] = r;
}

// ===========================================================================
// Float atomic max via int/uint ordering trick (no return -> RED).
// ===========================================================================
__device__ __forceinline__ void atomic_max_f(float* a, float v) {
    if (v >= 0.f)
        atomicMax((int*)a, __float_as_int(v));
    else
        atomicMin((unsigned int*)a, __float_as_uint(v));
}

// ===========================================================================
// Edge HMMA kernel, v12: fp16 C tile -> 5 CTAs/SM (20 warps, +25% latency
// hiding). C (32x64 fp16 = 4KB) fits entirely in the DEAD current-z buffer,
// so Cext is gone: per-warp smem 8KB, CTA 40KB, 5 CTAs = 200KB/SM.
// Sweep reads half2 per row and keeps the running max in half2 (HMAX2),
// converting to fp32 only at segment flush. Error: +~2.8e-4 RMS fp16-y
// term -> ~4e-4 total (2.4x under threshold).
// Otherwise v10: double-buffered z pipeline, dst-sorted contiguous chunks,
// fp16 MMA, SMEM-transpose epilogue, RED only at dst boundaries.
// ===========================================================================
__global__ __launch_bounds__(128, 5) void edge_mma_kernel(
    const float* __restrict__ W2, float* __restrict__ out, int E) {
    extern __shared__ char dsm[];

    const int tid = threadIdx.x;
    const int lane = tid & 31;
    const int wid = tid >> 5;

    // ---- build swizzled W2^T fp16 in SMEM (once per CTA) ----
    for (int i = tid; i < 64 * 64; i += 128) {
        int n = i >> 6, k = i & 63;
        float w = W2[k * 64 + n];
        uint32_t off = (uint32_t)n * 128 + (((uint32_t)(2 * k)) ^ ((uint32_t)(n & 7) << 4));
        *(__half*)(&dsm[off]) = __float2half_rn(w);
    }
    __syncthreads();

    const uint32_t w_base = smem_u32(&dsm[0]);
    const uint32_t wbuf = w_base + 8192 + (uint32_t)wid * 8192;
    const uint32_t zb0 = wbuf, zb1 = wbuf + 4096;

    // B-frag ldmatrix lane addressing (covers ks pair per x4)
    const uint32_t brow = lane & 7;
    const uint32_t bswz = brow << 4;
    const uint32_t bpart = (((uint32_t)lane >> 3) & 1) * 16 + (((uint32_t)lane >> 4) & 1) * 32;
    const uint32_t boff0 = brow * 128 + (bpart ^ bswz);        // ks0,ks1
    const uint32_t boff1 = brow * 128 + ((bpart + 64) ^ bswz); // ks2,ks3

    // A-frag ldmatrix lane addressing
    const int am = lane >> 3, rowin = lane & 7;
    const uint32_t lswz = (uint32_t)rowin << 4;
    const uint32_t akb = (uint32_t)((am >> 1) << 4);
    const int arow_in = ((am & 1) << 3) + rowin;

    // C-store lane addressing (fp16: row stride 128B, swz (r&7)<<4)
    const int crow = lane >> 2;                     // fragment row within 8
    const uint32_t ccb = (uint32_t)(lane & 3) * 4;  // col-pair bytes in n-tile
    const uint32_t cswz = (uint32_t)crow << 4;

    // cooperative-gather lane pieces: 4 edges per group, 8 lanes per edge
    const int sub = lane >> 3;                // which edge of the quad
    const int cq = lane & 7;                  // 16B chunk within 128B row
    const uint32_t cbyte = (uint32_t)cq * 16; // byte offset in fp16 row

    const __half2 zero2 = __float2half2_rn(0.f);

    // ---- contiguous chunk assignment ----
    const int T = (E + 31) >> 5;
    const int nwarp = gridDim.x * 4;
    const int gw = blockIdx.x * 4 + wid;
    const int chunk = (T + nwarp - 1) / nwarp;
    int t = gw * chunk;
    const int tend = (t + chunk < T) ? t + chunk : T;
    if (t >= tend) return;

    auto gather = [&](int2 sdv, uint32_t zdst) {
#pragma unroll 4
        for (int g = 0; g < 8; g++) {
            int esel = 4 * g + sub;
            int d = __shfl_sync(FULLM, sdv.y, esel);
            int s = __shfl_sync(FULLM, sdv.x, esel);
            uint4 pv = *((const uint4*)(g_PQh + (size_t)d * 128) + cq);
            uint4 qv = *((const uint4*)(g_PQh + (size_t)s * 128 + 64) + cq);
            __half2 z0 = __hmax2(__hadd2(*(__half2*)&pv.x, *(__half2*)&qv.x), zero2);
            __half2 z1 = __hmax2(__hadd2(*(__half2*)&pv.y, *(__half2*)&qv.y), zero2);
            __half2 z2 = __hmax2(__hadd2(*(__half2*)&pv.z, *(__half2*)&qv.z), zero2);
            __half2 z3 = __hmax2(__hadd2(*(__half2*)&pv.w, *(__half2*)&qv.w), zero2);
            uint32_t row = (uint32_t)(4 * g + sub);
            uint32_t off = row * 128 + (cbyte ^ ((row & 7) << 4));
            asm volatile("st.shared.v4.b32 [%0], {%1,%2,%3,%4};"
                         :: "r"(zdst + off),
                            "r"(*(uint32_t*)&z0), "r"(*(uint32_t*)&z1),
                            "r"(*(uint32_t*)&z2), "r"(*(uint32_t*)&z3));
        }
    };

    // ---- pipeline prologue ----
    int e0 = t * 32 + lane;
    int2 sd_cur = g_sorted[(e0 < E) ? e0 : 0];
    gather(sd_cur, zb0);
    int2 sd_nx = sd_cur;
    if (t + 1 < tend) {
        int en = (t + 1) * 32 + lane;
        sd_nx = g_sorted[(en < E) ? en : 0];
    }
    int p = 0;

    // running segmented-max state (carried across tiles, half2)
    int curD = -1;
    __half2 mh = zero2;

    for (; t < tend; t++) {
        int e = t * 32 + lane;
        bool valid = (e < E);
        int mydst = valid ? sd_cur.y : -1;
        uint32_t zcur = p ? zb1 : zb0;
        uint32_t znxt = p ? zb0 : zb1;

        __syncwarp();  // prev gather STS visible; prev sweep reads done

        // ---- A fragments for tile t from zcur ----
        uint32_t ah[8][4];  // [mt*4+ks]
#pragma unroll
        for (int mt = 0; mt < 2; mt++) {
            uint32_t rowb = (uint32_t)(mt * 16 + arow_in) * 128;
#pragma unroll
            for (int ks = 0; ks < 4; ks++) {
                uint32_t off = rowb + (((uint32_t)ks * 32 + akb) ^ lswz);
                ldmatrix_x4(ah[mt * 4 + ks], zcur + off);
            }
        }

        // ---- issue next tile's gather (overlaps with MMA below) ----
        bool more = (t + 1 < tend);
        if (more) gather(sd_nx, znxt);
        int2 sd_n2 = sd_nx;
        if (t + 2 < tend) {
            int en2 = (t + 2) * 32 + lane;
            sd_n2 = g_sorted[(en2 < E) ? en2 : 0];
        }

        // ---- MMA + fp16 C store into the dead zcur buffer ----
#pragma unroll
        for (int nt = 0; nt < 8; nt++) {
            uint32_t bw[4][2];
            uint32_t wb = (uint32_t)nt * 1024;
            ldmatrix_x4(&bw[0][0], w_base + wb + boff0);
            ldmatrix_x4(&bw[2][0], w_base + wb + boff1);
            uint32_t cb = (uint32_t)nt * 16 + ccb;
#pragma unroll
            for (int mt = 0; mt < 2; mt++) {
                float c[4] = {0.f, 0.f, 0.f, 0.f};
#pragma unroll
                for (int ks = 0; ks < 4; ks++) mma16816(c, ah[mt * 4 + ks], bw[ks]);

                __half2 c01 = __floats2half2_rn(c[0], c[1]);
                __half2 c23 = __floats2half2_rn(c[2], c[3]);
                uint32_t a0 = zcur + (uint32_t)(mt * 16 + crow) * 128 + (cb ^ cswz);
                asm volatile("st.shared.b32 [%0], %1;"
                             :: "r"(a0), "r"(*(uint32_t*)&c01));
                asm volatile("st.shared.b32 [%0], %1;"
                             :: "r"(a0 + 1024), "r"(*(uint32_t*)&c23));  // +8 rows
            }
        }
        __syncwarp();  // C stores visible before cross-lane reads

        // ---- serial 32-row sweep: running half2 max per col pair, RED at
        //      dst boundaries only ----
#pragma unroll 8
        for (int r = 0; r < 32; r++) {
            int d = __shfl_sync(FULLM, mydst, r);
            uint32_t off = zcur + (uint32_t)r * 128 +
                           (((uint32_t)lane * 4) ^ ((uint32_t)(r & 7) << 4));
            uint32_t yb;
            asm volatile("ld.shared.b32 %0, [%1];" : "=r"(yb) : "r"(off));
            __half2 y = *(__half2*)&yb;
            if (d < 0) continue;  // trailing invalid rows
            if (d != curD) {
                if (curD >= 0) {
                    float2 mf = __half22float2(mh);
                    float* o = out + (size_t)curD * 64 + lane * 2;
                    atomic_max_f(o, mf.x);
                    atomic_max_f(o + 1, mf.y);
                }
                curD = d;
                mh = y;
            } else {
                mh = __hmax2(mh, y);
            }
        }

        // ---- rotate pipeline ----
        sd_cur = sd_nx;
        sd_nx = sd_n2;
        p ^= 1;
    }

    // ---- final flush ----
    if (curD >= 0) {
        float2 mf = __half22float2(mh);
        float* o = out + (size_t)curD * 64 + lane * 2;
        atomic_max_f(o, mf.x);
        atomic_max_f(o + 1, mf.y);
    }
}

#define EDGE_DSMEM (8192 + 4 * 8192)

// ===========================================================================
// Inputs: [0]=xyz (N*3 f32), [1]=feat (N*64 f32), [2]=edge_index (2*E int),
//         [3]=W1 (134*64 f32), [4]=b1 (64), [5]=W2 (64*64), [6]=b2 (64)
// Launch DAG (multi-stream fork/join, graph-capturable):
//   s0: prep_init -> convhist -> scan1 -> scatter ─┐
//   s2: (fork) node_pq ────────────────────────────┴→ edge -> finalize
// ===========================================================================
extern "C" void kernel_launch(void* const* d_in, const int* in_sizes, int n_in,
                              void* d_out, int out_size) {
    const float* xyz  = (const float*)d_in[0];
    const float* feat = (const float*)d_in[1];
    const void*  eidx = d_in[2];
    const float* W1   = (const float*)d_in[3];
    const float* b1   = (const float*)d_in[4];
    const float* W2   = (const float*)d_in[5];
    const float* b2   = (const float*)d_in[6];
    float* out = (float*)d_out;

    int N = in_sizes[0] / 3;
    int E = in_sizes[2] / 2;
    int outn = N * 64;
    int n4 = outn / 4;
    int nb = (N + 1023) / 1024;
    int nbig = (n4 > N ? n4 : N);
    int nbp = (nbig + 1023) / 1024;

    static int inited = 0;
    static cudaStream_t s2;
    static cudaEvent_t evFork, evJoin;
    if (!inited) {
        cudaFuncSetAttribute(edge_mma_kernel,
                             cudaFuncAttributeMaxDynamicSharedMemorySize,
                             EDGE_DSMEM);
        cudaStreamCreateWithFlags(&s2, cudaStreamNonBlocking);
        cudaEventCreateWithFlags(&evFork, cudaEventDisableTiming);
        cudaEventCreateWithFlags(&evJoin, cudaEventDisableTiming);
        inited = 1;
    }

    // fork: node_pq on side stream (independent of the sort chain)
    cudaEventRecord(evFork, 0);
    cudaStreamWaitEvent(s2, evFork, 0);
    node_pq_kernel<<<(N + 31) / 32, 256, 0, s2>>>(xyz, feat, W1, b1, N);
    cudaEventRecord(evJoin, s2);

    // main chain
    prep_init_kernel<<<nbp, 1024>>>((const unsigned int*)eidx, (uint4*)out,
                                    N, n4);
    convhist_kernel<<<(E + 255) / 256, 256>>>(eidx, E);
    scan1_kernel<<<nb, 1024>>>(N);
    scatter_kernel<<<(E + 255) / 256, 256>>>(E);

    // join: edge needs both g_sorted (main) and g_PQh (side)
    cudaStreamWaitEvent(0, evJoin, 0);

    int Twarp = (E + 31) >> 5;
    int grid = 5 * 148;  // persistent, 5 CTAs/SM
    if (grid > (Twarp + 3) / 4) grid = (Twarp + 3) / 4;
    edge_mma_kernel<<<grid, 128, EDGE_DSMEM>>>(W2, out, E);

    finalize_kernel<<<(n4 + 255) / 256, 256>>>((uint4*)out, b2, n4);
}